// round 16
// baseline (speedup 1.0000x reference)
#include <cuda_runtime.h>
#include <cuda_fp16.h>

#define H    2048
#define D    2048
#define L    256
#define G3   (3*H)
#define GRID 148
#define THREADS 224
#define NWARP   7
#define UMAX    14
#define NB14    124          // 124*14 + 24*13 = 2048

#define WS_BYTES (NWARP*2*H*2)   // 57344: smem weight rows (n-gate of both units, per warp)

// ---- device globals (no allocations allowed) ----
__device__ float    g_u[G3], g_v[G3], g_c[G3];  // folded input-path coefficients
__device__ float    g_h[2][H];                  // double-buffered hidden state
__device__ unsigned g_bar;                      // monotonic arrival counter

// ---------------------------------------------------------------------------
// prep_fused: per-block computes p0/p1/pc in smem, folds W_ih into u/v/c.
// Block 0 resets g_bar (REQUIRED every graph replay) and writes out[0].
// x7 = [pk, tp, dose, emb0, emb1, emb2, route]
// ---------------------------------------------------------------------------
__global__ void prep_fused(const float* __restrict__ W_pre, const float* __restrict__ b_pre,
                           const float* __restrict__ dose,  const float* __restrict__ route,
                           const int*   __restrict__ pat_,  const float* __restrict__ emb_table,
                           const float* __restrict__ W_ih,  const float* __restrict__ b_ih,
                           const float* __restrict__ b_hh,  const float* __restrict__ pk_data,
                           float* __restrict__ out)
{
    __shared__ float p0[D], p1[D], pc[D];
    const int tid = threadIdx.x;
    const int pat = pat_[0];
    const float ds = dose[0], rt = route[0];
    const float e0 = emb_table[pat*3+0], e1 = emb_table[pat*3+1], e2 = emb_table[pat*3+2];
    for (int d = tid; d < D; d += 256) {
        const float* w = W_pre + d*7;
        p0[d] = w[0];
        p1[d] = w[1];
        pc[d] = ds*w[2] + e0*w[3] + e1*w[4] + e2*w[5] + rt*w[6] + b_pre[d];
    }
    if (blockIdx.x == 0 && tid == 0) { g_bar = 0u; out[0] = pk_data[0]; }
    __syncthreads();

    const int w = tid >> 5, lane = tid & 31;
    const int g = blockIdx.x * 8 + w;
    const float4* wr = (const float4*)(W_ih + (size_t)g * D);
    const float4* a4 = (const float4*)p0;
    const float4* b4 = (const float4*)p1;
    const float4* c4 = (const float4*)pc;
    float au = 0.f, av = 0.f, ac = 0.f;
    for (int i = lane; i < D/4; i += 32) {
        float4 wv = wr[i], A = a4[i], B = b4[i], C = c4[i];
        au += wv.x*A.x + wv.y*A.y + wv.z*A.z + wv.w*A.w;
        av += wv.x*B.x + wv.y*B.y + wv.z*B.z + wv.w*B.w;
        ac += wv.x*C.x + wv.y*C.y + wv.z*C.z + wv.w*C.w;
    }
    #pragma unroll
    for (int o = 16; o; o >>= 1) {
        au += __shfl_down_sync(0xffffffffu, au, o);
        av += __shfl_down_sync(0xffffffffu, av, o);
        ac += __shfl_down_sync(0xffffffffu, ac, o);
    }
    if (lane == 0) {
        g_u[g] = au; g_v[g] = av;
        float cc = ac + b_ih[g];
        if (g < 2*H) cc += b_hh[g];     // b_hh folds into r,z pre-activations only
        g_c[g] = cc;
    }
}

// ---------------------------------------------------------------------------
// Persistent GRU scan. Numerics frozen (fp16 weights / fp32 h / fp32 acc,
// identical per-accumulator FMA order). Hybrid weight residence:
// rows {r,z} of both units in REGISTERS (128 half2), rows {n} in SMEM
// (2 rows/warp) — relieves the R14 register spill while keeping LDS minimal.
// ---------------------------------------------------------------------------
__global__ void __launch_bounds__(THREADS, 1)
gru_kernel(const float* __restrict__ W_hh, const float* __restrict__ b_hh,
           const float* __restrict__ W_out, const float* __restrict__ b_out,
           const float* __restrict__ smiles, const float* __restrict__ pk_data,
           const float* __restrict__ timepoints, const int* __restrict__ tf_mask,
           float* __restrict__ out)
{
    extern __shared__ half ws[];         // [NWARP*2][H]: per-warp n-gate rows
    __shared__ float h_sm[H];            // staged h (fp32)
    __shared__ float wo_sm[H];           // full W_out
    __shared__ float tp_sm[L];
    __shared__ float pkd_sm[L];
    __shared__ int   tf_sm[L];
    __shared__ float cu[3*UMAX], cv[3*UMAX], ccs[3*UMAX];
    __shared__ float bhn[UMAX];
    __shared__ float ppart[NWARP];

    const int tid  = threadIdx.x;
    const int lane = tid & 31;
    const int w    = tid >> 5;
    const int b    = blockIdx.x;
    const int ustart = (b < NB14) ? 14*b : 14*NB14 + 13*(b - NB14);
    const int upb    = (b < NB14) ? 14 : 13;

    const int u0 = 2*w;                         // local units u0, u0+1
    int nu = upb - u0; nu = nu < 0 ? 0 : (nu > 2 ? 2 : nu);

    // ---- prologue: weight rows {r,z} -> REGISTERS (128 half2/thread) ----
    // wreg[rr*32 + ck*4 + q], rr=0..3 -> r={0,1,3,4} (unit-major, gates r,z),
    // covering k = ck*256 + lane*8 .. +8. Same values/k-map as before.
    half2 wreg[128];
    #pragma unroll
    for (int rr = 0; rr < 4; ++rr) {
        const int r    = (rr < 2) ? rr : rr + 1;    // 0,1,3,4
        const int lu   = u0 + r/3;
        const int gate = r - 3*(r/3);               // 0 or 1
        const bool valid = (r < 3) || (nu == 2);
        const float* wrow = W_hh + (size_t)(gate*H + ustart + lu) * H;
        #pragma unroll
        for (int ck = 0; ck < 8; ++ck) {
            const int k0 = ck*256 + lane*8;
            float4 a = make_float4(0.f,0.f,0.f,0.f), c = a;
            if (valid) {
                a = *(const float4*)(wrow + k0);
                c = *(const float4*)(wrow + k0 + 4);
            }
            wreg[rr*32 + ck*4 + 0] = __floats2half2_rn(a.x, a.y);
            wreg[rr*32 + ck*4 + 1] = __floats2half2_rn(a.z, a.w);
            wreg[rr*32 + ck*4 + 2] = __floats2half2_rn(c.x, c.y);
            wreg[rr*32 + ck*4 + 3] = __floats2half2_rn(c.z, c.w);
        }
    }
    // ---- n-gate rows (r=2 local unit u0; r=5 local unit u0+1) -> SMEM ----
    #pragma unroll
    for (int sr = 0; sr < 2; ++sr) {
        const int lu = u0 + sr;
        const bool valid = (sr == 0) || (nu == 2);
        const float* wrow = W_hh + (size_t)(2*H + ustart + lu) * H;
        half* dstrow = ws + (size_t)(w*2 + sr) * H;
        #pragma unroll
        for (int ck = 0; ck < 8; ++ck) {
            const int k0 = ck*256 + lane*8;
            float4 a = make_float4(0.f,0.f,0.f,0.f), c = a;
            if (valid) {
                a = *(const float4*)(wrow + k0);
                c = *(const float4*)(wrow + k0 + 4);
            }
            half2* dst = (half2*)(dstrow + k0);
            dst[0] = __floats2half2_rn(a.x, a.y);
            dst[1] = __floats2half2_rn(a.z, a.w);
            dst[2] = __floats2half2_rn(c.x, c.y);
            dst[3] = __floats2half2_rn(c.z, c.w);
        }
    }

    for (int j = tid; j < upb*3; j += THREADS) {
        int lu = j/3, gate = j - 3*lu;
        int grow = gate*H + ustart + lu;
        cu[j] = g_u[grow]; cv[j] = g_v[grow]; ccs[j] = g_c[grow];
    }
    for (int j = tid; j < upb; j += THREADS) bhn[j] = b_hh[2*H + ustart + j];
    for (int k = tid; k < H; k += THREADS) wo_sm[k] = W_out[k];
    for (int k = tid; k < L; k += THREADS) {
        tp_sm[k]  = timepoints[k];
        pkd_sm[k] = pk_data[k];
        tf_sm[k]  = tf_mask[k];
    }
    const float bo = b_out[0];
    const float4* wo4 = (const float4*)wo_sm;
    const half* wsn0 = ws + (size_t)(w*2 + 0) * H;   // n-row, unit u0
    const half* wsn1 = ws + (size_t)(w*2 + 1) * H;   // n-row, unit u0+1
    __syncthreads();

    for (int t = 0; t < L-1; ++t) {
        // A: stage h_{t-1} (L1-bypass, MLP=3) and fold pred = wo.h from the
        //    SAME registers.
        const float4* hsrc = (const float4*)((t == 0) ? smiles : g_h[(t-1)&1]);
        float4* hd = (float4*)h_sm;
        const float4 v0 = __ldcg(hsrc + tid);
        const float4 v1 = __ldcg(hsrc + tid + 224);
        float4 v2 = make_float4(0.f, 0.f, 0.f, 0.f);
        if (tid < 64) v2 = __ldcg(hsrc + tid + 448);
        hd[tid]       = v0;
        hd[tid + 224] = v1;
        if (tid < 64) hd[tid + 448] = v2;
        {
            const float4 q0 = wo4[tid];
            const float4 q1 = wo4[tid + 224];
            float sp = q0.x*v0.x + q0.y*v0.y + q0.z*v0.z + q0.w*v0.w
                     + q1.x*v1.x + q1.y*v1.y + q1.z*v1.z + q1.w*v1.w;
            if (tid < 64) {
                const float4 q2 = wo4[tid + 448];
                sp += q2.x*v2.x + q2.y*v2.y + q2.z*v2.z + q2.w*v2.w;
            }
            #pragma unroll
            for (int o = 16; o; o >>= 1) sp += __shfl_xor_sync(0xffffffffu, sp, o);
            if (lane == 0) ppart[w] = sp;
        }
        __syncthreads();                                   // h_sm + ppart ready

        const float pred = ((ppart[0]+ppart[1])+(ppart[2]+ppart[3]))
                         + ((ppart[4]+ppart[5])+ppart[6]) + bo;  // identical everywhere
        if (b == 0 && tid == 0 && t > 0) out[t] = pred;
        const float pk = (t > 0 && tf_sm[t] == 1) ? pred : pkd_sm[t];
        const float tp = tp_sm[t];

        // C: 6 dot products — r/z weights from REGISTERS, n weights from SMEM,
        //    h from smem, fp32 accumulate (per-acc FMA order unchanged).
        float acc[6] = {0.f,0.f,0.f,0.f,0.f,0.f};
        #pragma unroll
        for (int ck = 0; ck < 8; ++ck) {
            const int k0 = ck*256 + lane*8;
            const float4 ha = *(const float4*)(h_sm + k0);
            const float4 hb = *(const float4*)(h_sm + k0 + 4);
            // register rows: r=0,1 (unit u0 r,z), r=3,4 (unit u0+1 r,z)
            #pragma unroll
            for (int rr = 0; rr < 4; ++rr) {
                const int r = (rr < 2) ? rr : rr + 1;
                const float2 f0 = __half22float2(wreg[rr*32 + ck*4 + 0]);
                const float2 f1 = __half22float2(wreg[rr*32 + ck*4 + 1]);
                const float2 f2 = __half22float2(wreg[rr*32 + ck*4 + 2]);
                const float2 f3 = __half22float2(wreg[rr*32 + ck*4 + 3]);
                acc[r] = fmaf(f0.x, ha.x, acc[r]); acc[r] = fmaf(f0.y, ha.y, acc[r]);
                acc[r] = fmaf(f1.x, ha.z, acc[r]); acc[r] = fmaf(f1.y, ha.w, acc[r]);
                acc[r] = fmaf(f2.x, hb.x, acc[r]); acc[r] = fmaf(f2.y, hb.y, acc[r]);
                acc[r] = fmaf(f3.x, hb.z, acc[r]); acc[r] = fmaf(f3.y, hb.w, acc[r]);
            }
            // smem rows: r=2 (unit u0 n), r=5 (unit u0+1 n)
            {
                const uint4 wv = *(const uint4*)(wsn0 + k0);
                const float2 f0 = __half22float2(*(const half2*)&wv.x);
                const float2 f1 = __half22float2(*(const half2*)&wv.y);
                const float2 f2 = __half22float2(*(const half2*)&wv.z);
                const float2 f3 = __half22float2(*(const half2*)&wv.w);
                acc[2] = fmaf(f0.x, ha.x, acc[2]); acc[2] = fmaf(f0.y, ha.y, acc[2]);
                acc[2] = fmaf(f1.x, ha.z, acc[2]); acc[2] = fmaf(f1.y, ha.w, acc[2]);
                acc[2] = fmaf(f2.x, hb.x, acc[2]); acc[2] = fmaf(f2.y, hb.y, acc[2]);
                acc[2] = fmaf(f3.x, hb.z, acc[2]); acc[2] = fmaf(f3.y, hb.w, acc[2]);
            }
            {
                const uint4 wv = *(const uint4*)(wsn1 + k0);
                const float2 f0 = __half22float2(*(const half2*)&wv.x);
                const float2 f1 = __half22float2(*(const half2*)&wv.y);
                const float2 f2 = __half22float2(*(const half2*)&wv.z);
                const float2 f3 = __half22float2(*(const half2*)&wv.w);
                acc[5] = fmaf(f0.x, ha.x, acc[5]); acc[5] = fmaf(f0.y, ha.y, acc[5]);
                acc[5] = fmaf(f1.x, ha.z, acc[5]); acc[5] = fmaf(f1.y, ha.w, acc[5]);
                acc[5] = fmaf(f2.x, hb.x, acc[5]); acc[5] = fmaf(f2.y, hb.y, acc[5]);
                acc[5] = fmaf(f3.x, hb.z, acc[5]); acc[5] = fmaf(f3.y, hb.w, acc[5]);
            }
        }
        // butterfly: every lane ends with all 6 full sums (enables split gates)
        #pragma unroll
        for (int o = 16; o; o >>= 1) {
            #pragma unroll
            for (int r = 0; r < 6; ++r)
                acc[r] += __shfl_xor_sync(0xffffffffu, acc[r], o);
        }

        // D: gate math split across lane0 (unit u0) and lane16 (unit u0+1)
        if ((lane == 0) || (lane == 16 && nu == 2)) {
            const int un = (lane == 0) ? 0 : 1;
            const int j = u0 + un, cb = j*3;
            const float dr = acc[un*3], dz = acc[un*3+1], dn = acc[un*3+2];
            const float ar = fmaf(pk, cu[cb],   fmaf(tp, cv[cb],   ccs[cb]))   + dr;
            const float az = fmaf(pk, cu[cb+1], fmaf(tp, cv[cb+1], ccs[cb+1])) + dz;
            const float r  = 1.f/(1.f + __expf(-ar));
            const float z  = 1.f/(1.f + __expf(-az));
            const float an = fmaf(pk, cu[cb+2], fmaf(tp, cv[cb+2], ccs[cb+2]))
                           + r*(dn + bhn[j]);
            const float n  = tanhf(an);
            const float hnew = fmaf(1.f - z, n, z * h_sm[ustart + j]);
            g_h[t&1][ustart + j] = hnew;
        }
        __syncthreads();                                   // all h stores issued

        // E: minimal grid barrier (R1/R6/R10-proven pattern — frozen)
        if (tid == 0) {
            __threadfence();                               // release h stores
            atomicAdd(&g_bar, 1u);                         // RED (result unused)
            const unsigned target = (unsigned)GRID * (unsigned)(t+1);
            volatile unsigned* vb = &g_bar;
            while (*vb < target) { }
            __threadfence();                               // acquire others' h
        }
        __syncthreads();
    }

    // epilogue: out[255] = W_out . h_final + bo  (block 0 only)
    if (b == 0) {
        const float4* hsrc = (const float4*)g_h[(L-2)&1];
        float4* hd = (float4*)h_sm;
        for (int i = tid; i < H/4; i += THREADS) hd[i] = __ldcg(hsrc + i);
        __syncthreads();
        float s = 0.f;
        for (int k = tid; k < H; k += THREADS) s = fmaf(wo_sm[k], h_sm[k], s);
        #pragma unroll
        for (int o = 16; o; o >>= 1) s += __shfl_xor_sync(0xffffffffu, s, o);
        if (lane == 0) ppart[w] = s;
        __syncthreads();
        if (tid == 0)
            out[L-1] = ((ppart[0]+ppart[1])+(ppart[2]+ppart[3]))
                     + ((ppart[4]+ppart[5])+ppart[6]) + bo;
    }
}

// ---------------------------------------------------------------------------
// Inputs: 0 timepoints, 1 pk_data, 2 input_len, 3 emb_patient, 4 drug_route,
// 5 dose, 6 smiles, 7 tf_mask, 8 emb_table, 9 W_pre, 10 b_pre, 11 W_ih,
// 12 W_hh, 13 b_ih, 14 b_hh, 15 W_out, 16 b_out
// ---------------------------------------------------------------------------
extern "C" void kernel_launch(void* const* d_in, const int* in_sizes, int n_in,
                              void* d_out, int out_size)
{
    const float* timepoints = (const float*)d_in[0];
    const float* pk_data    = (const float*)d_in[1];
    const int*   pat        = (const int*)  d_in[3];
    const float* route      = (const float*)d_in[4];
    const float* dose       = (const float*)d_in[5];
    const float* smiles     = (const float*)d_in[6];
    const int*   tf_mask    = (const int*)  d_in[7];
    const float* emb_table  = (const float*)d_in[8];
    const float* W_pre      = (const float*)d_in[9];
    const float* b_pre      = (const float*)d_in[10];
    const float* W_ih       = (const float*)d_in[11];
    const float* W_hh       = (const float*)d_in[12];
    const float* b_ih       = (const float*)d_in[13];
    const float* b_hh       = (const float*)d_in[14];
    const float* W_out      = (const float*)d_in[15];
    const float* b_out      = (const float*)d_in[16];
    float* out = (float*)d_out;

    cudaFuncSetAttribute(gru_kernel, cudaFuncAttributeMaxDynamicSharedMemorySize, WS_BYTES);

    prep_fused<<<G3/8, 256>>>(W_pre, b_pre, dose, route, pat, emb_table,
                              W_ih, b_ih, b_hh, pk_data, out);
    gru_kernel<<<GRID, THREADS, WS_BYTES>>>(W_hh, b_hh, W_out, b_out, smiles,
                                            pk_data, timepoints, tf_mask, out);
}